// round 2
// baseline (speedup 1.0000x reference)
#include <cuda_runtime.h>
#include <cuda_bf16.h>

// LovaszSoftmaxLoss via quantized counting-sort (16384 bins).
// Math: Lovasz extension is 1-Lipschitz (inf-norm), grads >= 0 sum to 1, and
// tie-blocks contribute e*(J_end - J_start) independent of intra-block order.
// => quantize err to 14 bits (error <= 2^-15 ~ 3e-5 << 1e-3 tolerance) and
// replace the 19 argsorts of 4.19M elems with per-class histograms.

#define NUM_CLASSES 19
#define IGNORE_INDEX 255
#define HW_SHIFT 19                 // H*W = 512*1024 = 2^19
#define HW (1 << HW_SHIFT)
#define NPIX (8 * HW)               // 4,194,304
#define NBINS 16384
#define NBINS_M1 16383

// Scratch (no runtime allocation allowed): per-class histograms.
// low 32 bits: valid count, high 32 bits: fg count.
__device__ unsigned long long g_hist[NUM_CLASSES * NBINS];
__device__ double g_loss_sum;
__device__ double g_present;

// ---------------------------------------------------------------------------
__global__ void zero_kernel() {
    int i = blockIdx.x * blockDim.x + threadIdx.x;
    if (i < NUM_CLASSES * NBINS) g_hist[i] = 0ULL;
    if (i == 0) { g_loss_sum = 0.0; g_present = 0.0; }
}

// ---------------------------------------------------------------------------
// One thread per pixel: 19 coalesced logit loads (stride HW), softmax in
// registers, one 64-bit REDG per (pixel, class).
__global__ __launch_bounds__(256) void hist_kernel(
    const float* __restrict__ logits,
    const int* __restrict__ labels)     // harness delivers integer inputs as int32
{
    int n = blockIdx.x * blockDim.x + threadIdx.x;
    if (n >= NPIX) return;

    int lab = labels[n];

    int b  = n >> HW_SHIFT;
    int hw = n & (HW - 1);
    const float* base = logits + ((long long)b * NUM_CLASSES << HW_SHIFT) + hw;

    float x[NUM_CLASSES];
    float m = -1e30f;
#pragma unroll
    for (int c = 0; c < NUM_CLASSES; c++) {
        x[c] = __ldg(base + ((long long)c << HW_SHIFT));
        m = fmaxf(m, x[c]);
    }
    float s = 0.f;
#pragma unroll
    for (int c = 0; c < NUM_CLASSES; c++) {
        x[c] = __expf(x[c] - m);
        s += x[c];
    }

    if (lab == IGNORE_INDEX || lab < 0 || lab >= NUM_CLASSES) return;

    float inv = 1.0f / s;
#pragma unroll
    for (int c = 0; c < NUM_CLASSES; c++) {
        float p = x[c] * inv;
        bool fg = (c == lab);
        float err = fg ? (1.0f - p) : p;
        err = fminf(fmaxf(err, 0.0f), 1.0f);
        int bin = (int)(err * (float)NBINS_M1 + 0.5f);
        unsigned long long add = 1ULL | (fg ? (1ULL << 32) : 0ULL);
        atomicAdd(&g_hist[c * NBINS + bin], add);
    }
}

// ---------------------------------------------------------------------------
// One block per class. Threads cover descending bin order; block-scan gives
// exclusive prefix (F, V); fp64 Jaccard per nonempty bin.
__global__ __launch_bounds__(256) void reduce_kernel()
{
    const int c = blockIdx.x;
    const int t = threadIdx.x;          // 256 threads * 64 bins = 16384
    const unsigned long long* __restrict__ h = g_hist + c * NBINS;

    // pass 1: local sums over my 64 descending-order bins
    unsigned int sv = 0, sf = 0;
    for (int k = 0; k < 64; k++) {
        int bin = NBINS_M1 - (t * 64 + k);
        unsigned long long hv = h[bin];
        sv += (unsigned int)hv;
        sf += (unsigned int)(hv >> 32);
    }

    // inclusive warp scan
    unsigned int iv = sv, ifg = sf;
#pragma unroll
    for (int d = 1; d < 32; d <<= 1) {
        unsigned int tv = __shfl_up_sync(0xffffffffu, iv, d);
        unsigned int tf = __shfl_up_sync(0xffffffffu, ifg, d);
        if ((t & 31) >= d) { iv += tv; ifg += tf; }
    }
    __shared__ unsigned int wsv[8], wsf[8];
    if ((t & 31) == 31) { wsv[t >> 5] = iv; wsf[t >> 5] = ifg; }
    __syncthreads();

    unsigned int offv = 0, offf = 0, totV = 0, totF = 0;
#pragma unroll
    for (int w = 0; w < 8; w++) {
        unsigned int wv = wsv[w], wf = wsf[w];
        if (w < (t >> 5)) { offv += wv; offf += wf; }
        totV += wv; totF += wf;
    }
    unsigned int exclV = offv + iv - sv;   // valid count before my range
    unsigned int exclF = offf + ifg - sf;  // fg count before my range
    (void)totV;

    // pass 2: per-bin Lovasz terms (fp64 for stable tiny Jaccard deltas)
    double loss = 0.0;
    if (totF > 0) {
        const double G = (double)totF;
        double F = (double)exclF;
        double V = (double)exclV;
        double Jprev = 1.0 - (G - F) / (G + V - F);  // union >= G > 0 always
        const double escale = 1.0 / (double)NBINS_M1;
        for (int k = 0; k < 64; k++) {
            int bin = NBINS_M1 - (t * 64 + k);
            unsigned long long hv = h[bin];
            unsigned int v = (unsigned int)hv;
            unsigned int f = (unsigned int)(hv >> 32);
            if (v) {
                F += (double)f;
                V += (double)v;
                double J = 1.0 - (G - F) / (G + V - F);
                loss += (double)bin * escale * (J - Jprev);
                Jprev = J;
            }
        }
    }

    // block reduce loss (fp64)
#pragma unroll
    for (int d = 16; d > 0; d >>= 1)
        loss += __shfl_down_sync(0xffffffffu, loss, d);
    __shared__ double wloss[8];
    if ((t & 31) == 0) wloss[t >> 5] = loss;
    __syncthreads();
    if (t == 0) {
        double bl = 0.0;
#pragma unroll
        for (int w = 0; w < 8; w++) bl += wloss[w];
        if (totF > 0) {
            atomicAdd(&g_loss_sum, bl);
            atomicAdd(&g_present, 1.0);
        }
    }
}

// ---------------------------------------------------------------------------
__global__ void finalize_kernel(float* __restrict__ out)
{
    double np = g_present;
    if (np < 1.0) np = 1.0;
    out[0] = (float)(g_loss_sum / np);
}

// ---------------------------------------------------------------------------
extern "C" void kernel_launch(void* const* d_in, const int* in_sizes, int n_in,
                              void* d_out, int out_size)
{
    const float* logits = (const float*)d_in[0];
    const int*   labels = (const int*)d_in[1];
    float*       out    = (float*)d_out;

    (void)in_sizes; (void)n_in; (void)out_size;

    const int zn = NUM_CLASSES * NBINS;
    zero_kernel<<<(zn + 255) / 256, 256>>>();
    hist_kernel<<<NPIX / 256, 256>>>(logits, labels);
    reduce_kernel<<<NUM_CLASSES, 256>>>();
    finalize_kernel<<<1, 1>>>(out);
}